// round 10
// baseline (speedup 1.0000x reference)
#include <cuda_runtime.h>
#include <cuda_bf16.h>
#include <cstdint>

// ---------------------------------------------------------------------------
// CopyBackProjection: 6 chained sparse 3x3x3 convolutions on a shared
// neighbor map.
//   1. Compact (mask, nbr) once per launch into CSR entries (k<<20 | src).
//   2. Fold tile(x,4) into Wd0; "upsampled + r" folded into conv6 epilogue.
//   3. bf16 residual path (measured rel_err 1.6e-5, 60x under threshold).
//   4. Weights in SMEM as bf16x2 ci-pairs, HFMA2 math.
//   5. Per-block CSR tile staging into SMEM (meta + contiguous entry
//      segment, coalesced) -> kills the meta->entry->gather dependent chain
//      that made R3 latency-bound; pairwise entry unroll doubles gather MLP.
//   6. 1024-voxel tiles for light convs (~31KB smem) -> ~7 blocks/SM.
// ---------------------------------------------------------------------------

#define N_MAX (1 << 20)
#define KK 27

typedef unsigned int u32;

__device__ int g_entries[KK * N_MAX];
__device__ int g_meta[N_MAX];  // (off<<5)|cnt
__device__ int g_blockSums[4096];
__device__ int g_maskIsByte;
__device__ int g_totalEntries;
__device__ float g_W1[KK * 8 * 32];  // folded Wd0
__device__ __align__(16) __nv_bfloat16 g_buf32[(size_t)N_MAX * 32];  // 64 MB
__device__ __align__(16) __nv_bfloat16 g_buf8a[(size_t)N_MAX * 8];   // 16 MB
__device__ __align__(16) __nv_bfloat16 g_buf8b[(size_t)N_MAX * 8];   // 16 MB

__device__ __forceinline__ __nv_bfloat162 bf2(u32 u) {
    __nv_bfloat162 h;
    *reinterpret_cast<u32*>(&h) = u;
    return h;
}
__device__ __forceinline__ u32 pk(float a, float b) {
    __nv_bfloat162 h = __floats2bfloat162_rn(a, b);
    return *reinterpret_cast<u32*>(&h);
}
__device__ __forceinline__ float sum2(__nv_bfloat162 a) {
    float2 f = __bfloat1622float2(a);
    return f.x + f.y;
}
__device__ __forceinline__ int maskAt(const void* m, size_t idx) {
    return g_maskIsByte ? (((const unsigned char*)m)[idx] != 0)
                        : (((const u32*)m)[idx] != 0u);
}

// ---------------------------------------------------------------------------
// Mask dtype probe (bool-u8 vs 4-byte encodings).
// ---------------------------------------------------------------------------
__global__ void probe_mask_kernel(const unsigned char* __restrict__ m) {
    __shared__ int sAligned, sUnaligned;
    if (threadIdx.x == 0) { sAligned = 0; sUnaligned = 0; }
    __syncthreads();
    int a = 0, u = 0;
    for (int i = threadIdx.x; i < 4096; i += 256) {
        if (m[i] != 0) {
            if ((i & 3) == 0) a = 1;
            else u = 1;
        }
    }
    if (a) atomicOr(&sAligned, 1);
    if (u) atomicOr(&sUnaligned, 1);
    __syncthreads();
    if (threadIdx.x == 0) g_maskIsByte = (sAligned && sUnaligned) ? 1 : 0;
}

// ---------------------------------------------------------------------------
// Compaction: count -> scan -> fill
// ---------------------------------------------------------------------------

__global__ void count_kernel(const void* __restrict__ mask, int N) {
    int tid = threadIdx.x;
    int n = blockIdx.x * 256 + tid;
    int cnt = 0;
    if (n < N) {
        size_t NN = (size_t)N;
#pragma unroll
        for (int k = 0; k < KK; k++) cnt += maskAt(mask, (size_t)k * NN + n);
        g_meta[n] = cnt;
    }
    int s = cnt;
#pragma unroll
    for (int o = 16; o > 0; o >>= 1) s += __shfl_down_sync(0xffffffffu, s, o);
    __shared__ int ws[8];
    if ((tid & 31) == 0) ws[tid >> 5] = s;
    __syncthreads();
    if (tid == 0) {
        int tot = 0;
#pragma unroll
        for (int i = 0; i < 8; i++) tot += ws[i];
        g_blockSums[blockIdx.x] = tot;
    }
}

__global__ void scan_blocks_kernel(int nb) {
    int tid = threadIdx.x;
    int base = tid * 4;
    int v[4];
#pragma unroll
    for (int i = 0; i < 4; i++) v[i] = (base + i < nb) ? g_blockSums[base + i] : 0;
    int tsum = v[0] + v[1] + v[2] + v[3];
    int lane = tid & 31, wid = tid >> 5;
    int x = tsum;
#pragma unroll
    for (int o = 1; o < 32; o <<= 1) {
        int y = __shfl_up_sync(0xffffffffu, x, o);
        if (lane >= o) x += y;
    }
    __shared__ int ws[32];
    __shared__ int wsx[32];
    if (lane == 31) ws[wid] = x;
    __syncthreads();
    if (tid < 32) {
        int vv = ws[tid];
        int xx = vv;
#pragma unroll
        for (int o = 1; o < 32; o <<= 1) {
            int y = __shfl_up_sync(0xffffffffu, xx, o);
            if (tid >= o) xx += y;
        }
        wsx[tid] = xx - vv;
    }
    __syncthreads();
    int run = wsx[wid] + (x - tsum);
#pragma unroll
    for (int i = 0; i < 4; i++) {
        int old = v[i];
        if (base + i < nb) g_blockSums[base + i] = run;
        run += old;
    }
}

__global__ void fill_kernel(const void* __restrict__ mask,
                            const int* __restrict__ nbr, int N) {
    int tid = threadIdx.x;
    int n = blockIdx.x * 256 + tid;
    int cnt = (n < N) ? (g_meta[n]) : 0;
    int lane = tid & 31, wid = tid >> 5;
    int x = cnt;
#pragma unroll
    for (int o = 1; o < 32; o <<= 1) {
        int y = __shfl_up_sync(0xffffffffu, x, o);
        if (lane >= o) x += y;
    }
    __shared__ int ws[8];
    __shared__ int wsx[8];
    if (lane == 31) ws[wid] = x;
    __syncthreads();
    if (tid < 8) {
        int vv = ws[tid];
        int xx = vv;
#pragma unroll
        for (int o = 1; o < 8; o <<= 1) {
            int y = __shfl_up_sync(0x000000ffu, xx, o);
            if (tid >= o) xx += y;
        }
        wsx[tid] = xx - vv;
    }
    __syncthreads();
    int off = g_blockSums[blockIdx.x] + wsx[wid] + (x - cnt);
    if (n < N) {
        g_meta[n] = (off << 5) | cnt;
        if (n == N - 1) g_totalEntries = off + cnt;
        int w = off;
        size_t NN = (size_t)N;
#pragma unroll
        for (int k = 0; k < KK; k++) {
            if (maskAt(mask, (size_t)k * NN + n)) {
                g_entries[w++] = (k << 20) | nbr[(size_t)k * NN + n];
            }
        }
    }
}

// Fold tile(x,4) into Wd0: W1[k][ci][co] = sum_t Wd0[k][ci+8t][co]
__global__ void fold_kernel(const float* __restrict__ Wd0) {
    int i = blockIdx.x * 256 + threadIdx.x;
    if (i >= KK * 8 * 32) return;
    int co = i & 31;
    int ci = (i >> 5) & 7;
    int k = i >> 8;
    const float* base = Wd0 + (size_t)k * 1024 + co;
    g_W1[i] = base[ci * 32] + base[(ci + 8) * 32] + base[(ci + 16) * 32] +
              base[(ci + 24) * 32];
}

// ---------------------------------------------------------------------------
// CSR tile staging: meta + contiguous entry segment into SMEM.
// 1024-voxel tiles; entry buffer 3328 (mean 2611, +18 sigma); guarded
// fallback to global reads on overflow.  Boundary metas read redundantly by
// all threads (overlaps bulk staging; no extra barrier level).
// ---------------------------------------------------------------------------
#define TILE_V 1024
#define LOG_V 10
#define MAXE_V 3328

#define STAGE_TILE()                                                           \
    int base = tile << LOG_V;                                                  \
    int nv = min(TILE_V, N - base);                                            \
    int offStart = __ldg(g_meta + base) >> 5;                                  \
    int offEnd = (base + nv < N) ? (__ldg(g_meta + base + nv) >> 5)            \
                                 : g_totalEntries;                             \
    __syncthreads();                                                           \
    for (int t = threadIdx.x; t < nv; t += 256) sMeta[t] = g_meta[base + t];   \
    int nE = offEnd - offStart;                                                \
    bool useSm = (nE <= (MAXE_V));                                             \
    if (useSm)                                                                 \
        for (int t = threadIdx.x; t < nE; t += 256)                            \
            sEnt[t] = g_entries[offStart + t];                                 \
    __syncthreads();

// Pairwise entry loop over a voxel's entries; EMAC(e, accX, accY) per entry.
#define PAIR_LOOP(EMAC)                                                        \
    if (useSm) {                                                               \
        int j = 0;                                                             \
        for (; j + 2 <= cnt; j += 2) {                                         \
            int e0 = sEnt[ib + j], e1 = sEnt[ib + j + 1];                      \
            EMAC(e0, acc0, acc1);                                              \
            EMAC(e1, acc2, acc3);                                              \
        }                                                                      \
        if (j < cnt) {                                                         \
            int e0 = sEnt[ib + j];                                             \
            EMAC(e0, acc0, acc1);                                              \
        }                                                                      \
    } else {                                                                   \
        int gb = ib + offStart;                                                \
        int j = 0;                                                             \
        for (; j + 2 <= cnt; j += 2) {                                         \
            int e0 = __ldg(g_entries + gb + j), e1 = __ldg(g_entries + gb + j + 1); \
            EMAC(e0, acc0, acc1);                                              \
            EMAC(e1, acc2, acc3);                                              \
        }                                                                      \
        if (j < cnt) {                                                         \
            int e0 = __ldg(g_entries + gb + j);                                \
            EMAC(e0, acc0, acc1);                                              \
        }                                                                      \
    }

// ---------------------------------------------------------------------------
// conv1: x(f32,[N,8]) @ W1[27,8,32] -> g_buf32 (bf16).  lane = co.
// ---------------------------------------------------------------------------
__global__ void __launch_bounds__(256) convA_kernel(const float* __restrict__ x, int N) {
    __shared__ uint2 Wsh[KK * 64];
    __shared__ int sMeta[TILE_V];
    __shared__ int sEnt[MAXE_V];
    for (int t = threadIdx.x; t < KK * 64; t += 256) {
        int l = t & 31, jp = (t >> 5) & 1, k = t >> 6;
        const float* wb = g_W1 + (k << 8) + l;
        int c = jp * 4;
        uint2 u;
        u.x = pk(wb[c * 32], wb[(c + 1) * 32]);
        u.y = pk(wb[(c + 2) * 32], wb[(c + 3) * 32]);
        Wsh[t] = u;
    }
    int lane = threadIdx.x & 31, wid = threadIdx.x >> 5;
    int ntiles = (N + TILE_V - 1) >> LOG_V;
    for (int tile = blockIdx.x; tile < ntiles; tile += gridDim.x) {
        STAGE_TILE()
#define A_E(E, A0, A1)                                                    \
    {                                                                     \
        int k = (E) >> 20, s = (E) & 0xFFFFF;                             \
        const float4* p = reinterpret_cast<const float4*>(x + ((size_t)s << 3)); \
        float4 fa = __ldg(p), fb = __ldg(p + 1);                          \
        const uint2* wk = Wsh + (k << 6) + lane;                          \
        uint2 w0 = wk[0], w1 = wk[32];                                    \
        A0 = __hfma2(bf2(pk(fa.x, fa.y)), bf2(w0.x), A0);                 \
        A1 = __hfma2(bf2(pk(fa.z, fa.w)), bf2(w0.y), A1);                 \
        A0 = __hfma2(bf2(pk(fb.x, fb.y)), bf2(w1.x), A0);                 \
        A1 = __hfma2(bf2(pk(fb.z, fb.w)), bf2(w1.y), A1);                 \
    }
        for (int v = wid; v < nv; v += 8) {
            int m = sMeta[v];
            int cnt = m & 31, ib = (m >> 5) - offStart;
            __nv_bfloat162 acc0 = bf2(0u), acc1 = bf2(0u), acc2 = bf2(0u),
                           acc3 = bf2(0u);
            PAIR_LOOP(A_E)
            float r = (sum2(acc0) + sum2(acc1)) + (sum2(acc2) + sum2(acc3));
            g_buf32[((size_t)(base + v) << 5) + lane] = __float2bfloat16(r);
        }
#undef A_E
    }
}

// ---------------------------------------------------------------------------
// conv2: g_buf32(bf16,[N,32]) @ Wd1[27,32,8] -> g_buf8a.  co=lane&7,
// g=lane>>3 covers ci in [8g,8g+8).
// ---------------------------------------------------------------------------
__global__ void __launch_bounds__(256) convB_kernel(const float* __restrict__ W, int N) {
    __shared__ uint2 Wsh[KK * 64];
    __shared__ int sMeta[TILE_V];
    __shared__ int sEnt[MAXE_V];
    for (int t = threadIdx.x; t < KK * 64; t += 256) {
        int l = t & 31, jp = (t >> 5) & 1, k = t >> 6;
        int g = l >> 3, co = l & 7;
        const float* wb = W + (size_t)k * 256 + co;
        int c = g * 8 + jp * 4;
        uint2 u;
        u.x = pk(wb[c * 8], wb[(c + 1) * 8]);
        u.y = pk(wb[(c + 2) * 8], wb[(c + 3) * 8]);
        Wsh[t] = u;
    }
    int lane = threadIdx.x & 31, wid = threadIdx.x >> 5;
    int g = lane >> 3, co = lane & 7;
    int ntiles = (N + TILE_V - 1) >> LOG_V;
    for (int tile = blockIdx.x; tile < ntiles; tile += gridDim.x) {
        STAGE_TILE()
#define B_E(E, A0, A1)                                                    \
    {                                                                     \
        int k = (E) >> 20, s = (E) & 0xFFFFF;                             \
        uint4 q = __ldg(reinterpret_cast<const uint4*>(g_buf32 +          \
                                                       ((size_t)s << 5) + (g << 3))); \
        const uint2* wk = Wsh + (k << 6) + lane;                          \
        uint2 w0 = wk[0], w1 = wk[32];                                    \
        A0 = __hfma2(bf2(q.x), bf2(w0.x), A0);                            \
        A1 = __hfma2(bf2(q.y), bf2(w0.y), A1);                            \
        A0 = __hfma2(bf2(q.z), bf2(w1.x), A0);                            \
        A1 = __hfma2(bf2(q.w), bf2(w1.y), A1);                            \
    }
        for (int v = wid; v < nv; v += 8) {
            int m = sMeta[v];
            int cnt = m & 31, ib = (m >> 5) - offStart;
            __nv_bfloat162 acc0 = bf2(0u), acc1 = bf2(0u), acc2 = bf2(0u),
                           acc3 = bf2(0u);
            PAIR_LOOP(B_E)
            float acc = (sum2(acc0) + sum2(acc1)) + (sum2(acc2) + sum2(acc3));
            acc += __shfl_xor_sync(0xffffffffu, acc, 8);
            acc += __shfl_xor_sync(0xffffffffu, acc, 16);
            if (g == 0) g_buf8a[((size_t)(base + v) << 3) + co] = __float2bfloat16(acc);
        }
#undef B_E
    }
}

// ---------------------------------------------------------------------------
// conv3/conv4: 8->8.  SRC=0: buf8a->buf8b (RESID: out = x - conv),
// SRC=1: buf8b->buf8a.  co=lane&7, g=lane>>3 covers ci 2g,2g+1.
// ---------------------------------------------------------------------------
template <int SRC, int RESID>
__global__ void __launch_bounds__(256) conv88_kernel(const float* __restrict__ W,
                                                     const float* __restrict__ x, int N) {
    __shared__ u32 Wsh[KK * 32];
    __shared__ int sMeta[TILE_V];
    __shared__ int sEnt[MAXE_V];
    for (int t = threadIdx.x; t < KK * 32; t += 256) {
        int l = t & 31, k = t >> 5;
        int g = l >> 3, co = l & 7;
        const float* wb = W + (size_t)k * 64 + co;
        Wsh[t] = pk(wb[(2 * g) * 8], wb[(2 * g + 1) * 8]);
    }
    const __nv_bfloat16* in = (SRC == 0) ? g_buf8a : g_buf8b;
    __nv_bfloat16* out = (SRC == 0) ? g_buf8b : g_buf8a;
    int lane = threadIdx.x & 31, wid = threadIdx.x >> 5;
    int g = lane >> 3, co = lane & 7;
    int ntiles = (N + TILE_V - 1) >> LOG_V;
    for (int tile = blockIdx.x; tile < ntiles; tile += gridDim.x) {
        STAGE_TILE()
#define C_E(E, A0, A1)                                                    \
    {                                                                     \
        int k = (E) >> 20, s = (E) & 0xFFFFF;                             \
        u32 q = __ldg(reinterpret_cast<const u32*>(in + ((size_t)s << 3) + (g << 1))); \
        A0 = __hfma2(bf2(q), bf2(Wsh[(k << 5) + lane]), A0);              \
        (void)A1;                                                         \
    }
        for (int v = wid; v < nv; v += 8) {
            int m = sMeta[v];
            int cnt = m & 31, ib = (m >> 5) - offStart;
            __nv_bfloat162 acc0 = bf2(0u), acc1 = bf2(0u), acc2 = bf2(0u),
                           acc3 = bf2(0u);
            PAIR_LOOP(C_E)
            float acc = sum2(acc0) + sum2(acc2);
            acc += __shfl_xor_sync(0xffffffffu, acc, 8);
            acc += __shfl_xor_sync(0xffffffffu, acc, 16);
            if (g == 0) {
                float r = RESID ? (x[((size_t)(base + v) << 3) + co] - acc) : acc;
                out[((size_t)(base + v) << 3) + co] = __float2bfloat16(r);
            }
        }
#undef C_E
    }
}

// ---------------------------------------------------------------------------
// conv5: g_buf8a(bf16,[N,8]) @ Wu1[27,8,32] -> g_buf32.  lane = co.
// ---------------------------------------------------------------------------
__global__ void __launch_bounds__(256) convE_kernel(const float* __restrict__ W, int N) {
    __shared__ uint2 Wsh[KK * 64];
    __shared__ int sMeta[TILE_V];
    __shared__ int sEnt[MAXE_V];
    for (int t = threadIdx.x; t < KK * 64; t += 256) {
        int l = t & 31, jp = (t >> 5) & 1, k = t >> 6;
        const float* wb = W + (size_t)k * 256 + l;
        int c = jp * 4;
        uint2 u;
        u.x = pk(wb[c * 32], wb[(c + 1) * 32]);
        u.y = pk(wb[(c + 2) * 32], wb[(c + 3) * 32]);
        Wsh[t] = u;
    }
    int lane = threadIdx.x & 31, wid = threadIdx.x >> 5;
    int ntiles = (N + TILE_V - 1) >> LOG_V;
    for (int tile = blockIdx.x; tile < ntiles; tile += gridDim.x) {
        STAGE_TILE()
#define E_E(E, A0, A1)                                                    \
    {                                                                     \
        int k = (E) >> 20, s = (E) & 0xFFFFF;                             \
        uint4 q = __ldg(reinterpret_cast<const uint4*>(g_buf8a + ((size_t)s << 3))); \
        const uint2* wk = Wsh + (k << 6) + lane;                          \
        uint2 w0 = wk[0], w1 = wk[32];                                    \
        A0 = __hfma2(bf2(q.x), bf2(w0.x), A0);                            \
        A1 = __hfma2(bf2(q.y), bf2(w0.y), A1);                            \
        A0 = __hfma2(bf2(q.z), bf2(w1.x), A0);                            \
        A1 = __hfma2(bf2(q.w), bf2(w1.y), A1);                            \
    }
        for (int v = wid; v < nv; v += 8) {
            int m = sMeta[v];
            int cnt = m & 31, ib = (m >> 5) - offStart;
            __nv_bfloat162 acc0 = bf2(0u), acc1 = bf2(0u), acc2 = bf2(0u),
                           acc3 = bf2(0u);
            PAIR_LOOP(E_E)
            float r = (sum2(acc0) + sum2(acc1)) + (sum2(acc2) + sum2(acc3));
            g_buf32[((size_t)(base + v) << 5) + lane] = __float2bfloat16(r);
        }
#undef E_E
    }
}

// ---------------------------------------------------------------------------
// conv6: g_buf32(bf16,[N,32]) @ Wu2[27,32,32] -> d_out(f32), epilogue adds
// tile(x,4).  lane = co.  Dynamic smem: weights (54KB) + meta + entries.
// ---------------------------------------------------------------------------
#define WF_U2 (KK * 8 * 32)  // 6912 uint2
__global__ void __launch_bounds__(256) convF_kernel(const float* __restrict__ W,
                                                    const float* __restrict__ x,
                                                    float* __restrict__ out, int N) {
    extern __shared__ u32 dyn[];
    uint2* Wsh = reinterpret_cast<uint2*>(dyn);
    int* sMeta = reinterpret_cast<int*>(dyn + 2 * WF_U2);
    int* sEnt = sMeta + TILE_V;
    for (int t = threadIdx.x; t < WF_U2; t += 256) {
        int l = t & 31, ip = (t >> 5) & 7, k = t >> 8;
        const float* wb = W + (size_t)k * 1024 + l;
        int c = ip * 4;
        uint2 u;
        u.x = pk(wb[c * 32], wb[(c + 1) * 32]);
        u.y = pk(wb[(c + 2) * 32], wb[(c + 3) * 32]);
        Wsh[t] = u;
    }
    int lane = threadIdx.x & 31, wid = threadIdx.x >> 5;
    int ntiles = (N + TILE_V - 1) >> LOG_V;
    for (int tile = blockIdx.x; tile < ntiles; tile += gridDim.x) {
        STAGE_TILE()
#define F_E(E, A0, A1)                                                    \
    {                                                                     \
        int k = (E) >> 20, s = (E) & 0xFFFFF;                             \
        const uint4* p = reinterpret_cast<const uint4*>(g_buf32 + ((size_t)s << 5)); \
        uint4 q0 = __ldg(p), q1 = __ldg(p + 1), q2 = __ldg(p + 2), q3 = __ldg(p + 3); \
        const uint2* wk = Wsh + (k << 8) + lane;                          \
        uint2 w;                                                          \
        w = wk[0];                                                        \
        A0 = __hfma2(bf2(q0.x), bf2(w.x), A0);                            \
        A1 = __hfma2(bf2(q0.y), bf2(w.y), A1);                            \
        w = wk[32];                                                       \
        A0 = __hfma2(bf2(q0.z), bf2(w.x), A0);                            \
        A1 = __hfma2(bf2(q0.w), bf2(w.y), A1);                            \
        w = wk[64];                                                       \
        A0 = __hfma2(bf2(q1.x), bf2(w.x), A0);                            \
        A1 = __hfma2(bf2(q1.y), bf2(w.y), A1);                            \
        w = wk[96];                                                       \
        A0 = __hfma2(bf2(q1.z), bf2(w.x), A0);                            \
        A1 = __hfma2(bf2(q1.w), bf2(w.y), A1);                            \
        w = wk[128];                                                      \
        A0 = __hfma2(bf2(q2.x), bf2(w.x), A0);                            \
        A1 = __hfma2(bf2(q2.y), bf2(w.y), A1);                            \
        w = wk[160];                                                      \
        A0 = __hfma2(bf2(q2.z), bf2(w.x), A0);                            \
        A1 = __hfma2(bf2(q2.w), bf2(w.y), A1);                            \
        w = wk[192];                                                      \
        A0 = __hfma2(bf2(q3.x), bf2(w.x), A0);                            \
        A1 = __hfma2(bf2(q3.y), bf2(w.y), A1);                            \
        w = wk[224];                                                      \
        A0 = __hfma2(bf2(q3.z), bf2(w.x), A0);                            \
        A1 = __hfma2(bf2(q3.w), bf2(w.y), A1);                            \
    }
        for (int v = wid; v < nv; v += 8) {
            int m = sMeta[v];
            int cnt = m & 31, ib = (m >> 5) - offStart;
            __nv_bfloat162 acc0 = bf2(0u), acc1 = bf2(0u), acc2 = bf2(0u),
                           acc3 = bf2(0u);
            PAIR_LOOP(F_E)
            float acc = (sum2(acc0) + sum2(acc1)) + (sum2(acc2) + sum2(acc3));
            out[((size_t)(base + v) << 5) + lane] =
                acc + x[((size_t)(base + v) << 3) + (lane & 7)];
        }
#undef F_E
    }
}

// ---------------------------------------------------------------------------

extern "C" void kernel_launch(void* const* d_in, const int* in_sizes, int n_in,
                              void* d_out, int out_size) {
    const float* x = (const float*)d_in[0];
    const int* nbr = (const int*)d_in[1];
    const void* mask = d_in[2];
    const float* Wd0 = (const float*)d_in[3];
    const float* Wd1 = (const float*)d_in[4];
    const float* Wd2 = (const float*)d_in[5];
    const float* Wu0 = (const float*)d_in[6];
    const float* Wu1 = (const float*)d_in[7];
    const float* Wu2 = (const float*)d_in[8];
    float* out = (float*)d_out;

    int N = in_sizes[0] / 8;
    if (N > N_MAX) N = N_MAX;
    int nb = (N + 255) / 256;

    probe_mask_kernel<<<1, 256>>>((const unsigned char*)mask);
    count_kernel<<<nb, 256>>>(mask, N);
    scan_blocks_kernel<<<1, 1024>>>(nb);
    fill_kernel<<<nb, 256>>>(mask, nbr, N);
    fold_kernel<<<(KK * 8 * 32 + 255) / 256, 256>>>(Wd0);

    int ntL = (N + TILE_V - 1) >> LOG_V;  // one tile per block
    convA_kernel<<<ntL, 256>>>(x, N);
    convB_kernel<<<ntL, 256>>>(Wd1, N);
    conv88_kernel<0, 1><<<ntL, 256>>>(Wd2, x, N);  // d3, then r = x - d
    conv88_kernel<1, 0><<<ntL, 256>>>(Wu0, x, N);
    convE_kernel<<<ntL, 256>>>(Wu1, N);

    const int smF = (2 * WF_U2 + TILE_V + MAXE_V) * 4;  // ~72.7 KB
    cudaFuncSetAttribute(convF_kernel, cudaFuncAttributeMaxDynamicSharedMemorySize, smF);
    int gF = ntL < 444 ? ntL : 444;  // 3 blocks/SM persistent
    convF_kernel<<<gF, 256, smF>>>(Wu2, x, out, N);
}

// round 12
// speedup vs baseline: 1.1625x; 1.1625x over previous
#include <cuda_runtime.h>
#include <cuda_bf16.h>
#include <cstdint>

// ---------------------------------------------------------------------------
// CopyBackProjection: 6 chained sparse 3x3x3 convolutions on a shared
// neighbor map.  Base = R3 measured-best (1147us): persistent grid-stride
// warp-per-voxel convs, SMEM bf16x2 weights, HFMA2.
// Change under test (only): more independent memory chains per warp --
//   light convs: 2 voxels per warp iteration (dual meta/entry/gather chains)
//   convF: pairwise entry unroll into independent accumulator banks.
// Staged-CSR design from R10 measured 1466us (regression) -> abandoned.
// ---------------------------------------------------------------------------

#define N_MAX (1 << 20)
#define KK 27

typedef unsigned int u32;

__device__ int g_entries[KK * N_MAX];
__device__ int g_meta[N_MAX];  // (off<<5)|cnt
__device__ int g_blockSums[4096];
__device__ int g_maskIsByte;
__device__ int g_totalEntries;
__device__ float g_W1[KK * 8 * 32];  // folded Wd0
__device__ __align__(16) __nv_bfloat16 g_buf32[(size_t)N_MAX * 32];  // 64 MB
__device__ __align__(16) __nv_bfloat16 g_buf8a[(size_t)N_MAX * 8];   // 16 MB
__device__ __align__(16) __nv_bfloat16 g_buf8b[(size_t)N_MAX * 8];   // 16 MB

__device__ __forceinline__ __nv_bfloat162 bf2(u32 u) {
    __nv_bfloat162 h;
    *reinterpret_cast<u32*>(&h) = u;
    return h;
}
__device__ __forceinline__ u32 pk(float a, float b) {
    __nv_bfloat162 h = __floats2bfloat162_rn(a, b);
    return *reinterpret_cast<u32*>(&h);
}
__device__ __forceinline__ float sum2(__nv_bfloat162 a) {
    float2 f = __bfloat1622float2(a);
    return f.x + f.y;
}
__device__ __forceinline__ int maskAt(const void* m, size_t idx) {
    return g_maskIsByte ? (((const unsigned char*)m)[idx] != 0)
                        : (((const u32*)m)[idx] != 0u);
}

// ---------------------------------------------------------------------------
// Mask dtype probe (bool-u8 vs 4-byte encodings).
// ---------------------------------------------------------------------------
__global__ void probe_mask_kernel(const unsigned char* __restrict__ m) {
    __shared__ int sAligned, sUnaligned;
    if (threadIdx.x == 0) { sAligned = 0; sUnaligned = 0; }
    __syncthreads();
    int a = 0, u = 0;
    for (int i = threadIdx.x; i < 4096; i += 256) {
        if (m[i] != 0) {
            if ((i & 3) == 0) a = 1;
            else u = 1;
        }
    }
    if (a) atomicOr(&sAligned, 1);
    if (u) atomicOr(&sUnaligned, 1);
    __syncthreads();
    if (threadIdx.x == 0) g_maskIsByte = (sAligned && sUnaligned) ? 1 : 0;
}

// ---------------------------------------------------------------------------
// Compaction: count -> scan -> fill  (identical to measured-best)
// ---------------------------------------------------------------------------

__global__ void count_kernel(const void* __restrict__ mask, int N) {
    int tid = threadIdx.x;
    int n = blockIdx.x * 256 + tid;
    int cnt = 0;
    if (n < N) {
        size_t NN = (size_t)N;
#pragma unroll
        for (int k = 0; k < KK; k++) cnt += maskAt(mask, (size_t)k * NN + n);
        g_meta[n] = cnt;
    }
    int s = cnt;
#pragma unroll
    for (int o = 16; o > 0; o >>= 1) s += __shfl_down_sync(0xffffffffu, s, o);
    __shared__ int ws[8];
    if ((tid & 31) == 0) ws[tid >> 5] = s;
    __syncthreads();
    if (tid == 0) {
        int tot = 0;
#pragma unroll
        for (int i = 0; i < 8; i++) tot += ws[i];
        g_blockSums[blockIdx.x] = tot;
    }
}

__global__ void scan_blocks_kernel(int nb) {
    int tid = threadIdx.x;
    int base = tid * 4;
    int v[4];
#pragma unroll
    for (int i = 0; i < 4; i++) v[i] = (base + i < nb) ? g_blockSums[base + i] : 0;
    int tsum = v[0] + v[1] + v[2] + v[3];
    int lane = tid & 31, wid = tid >> 5;
    int x = tsum;
#pragma unroll
    for (int o = 1; o < 32; o <<= 1) {
        int y = __shfl_up_sync(0xffffffffu, x, o);
        if (lane >= o) x += y;
    }
    __shared__ int ws[32];
    __shared__ int wsx[32];
    if (lane == 31) ws[wid] = x;
    __syncthreads();
    if (tid < 32) {
        int vv = ws[tid];
        int xx = vv;
#pragma unroll
        for (int o = 1; o < 32; o <<= 1) {
            int y = __shfl_up_sync(0xffffffffu, xx, o);
            if (tid >= o) xx += y;
        }
        wsx[tid] = xx - vv;
    }
    __syncthreads();
    int run = wsx[wid] + (x - tsum);
#pragma unroll
    for (int i = 0; i < 4; i++) {
        int old = v[i];
        if (base + i < nb) g_blockSums[base + i] = run;
        run += old;
    }
}

__global__ void fill_kernel(const void* __restrict__ mask,
                            const int* __restrict__ nbr, int N) {
    int tid = threadIdx.x;
    int n = blockIdx.x * 256 + tid;
    int cnt = (n < N) ? (g_meta[n]) : 0;
    int lane = tid & 31, wid = tid >> 5;
    int x = cnt;
#pragma unroll
    for (int o = 1; o < 32; o <<= 1) {
        int y = __shfl_up_sync(0xffffffffu, x, o);
        if (lane >= o) x += y;
    }
    __shared__ int ws[8];
    __shared__ int wsx[8];
    if (lane == 31) ws[wid] = x;
    __syncthreads();
    if (tid < 8) {
        int vv = ws[tid];
        int xx = vv;
#pragma unroll
        for (int o = 1; o < 8; o <<= 1) {
            int y = __shfl_up_sync(0x000000ffu, xx, o);
            if (tid >= o) xx += y;
        }
        wsx[tid] = xx - vv;
    }
    __syncthreads();
    int off = g_blockSums[blockIdx.x] + wsx[wid] + (x - cnt);
    if (n < N) {
        g_meta[n] = (off << 5) | cnt;
        if (n == N - 1) g_totalEntries = off + cnt;
        int w = off;
        size_t NN = (size_t)N;
#pragma unroll
        for (int k = 0; k < KK; k++) {
            if (maskAt(mask, (size_t)k * NN + n)) {
                g_entries[w++] = (k << 20) | nbr[(size_t)k * NN + n];
            }
        }
    }
}

// Fold tile(x,4) into Wd0: W1[k][ci][co] = sum_t Wd0[k][ci+8t][co]
__global__ void fold_kernel(const float* __restrict__ Wd0) {
    int i = blockIdx.x * 256 + threadIdx.x;
    if (i >= KK * 8 * 32) return;
    int co = i & 31;
    int ci = (i >> 5) & 7;
    int k = i >> 8;
    const float* base = Wd0 + (size_t)k * 1024 + co;
    g_W1[i] = base[ci * 32] + base[(ci + 8) * 32] + base[(ci + 16) * 32] +
              base[(ci + 24) * 32];
}

// ---------------------------------------------------------------------------
// Dual-voxel loop for light convs: two independent meta/entry/gather chains.
// EMAC(e, P0, P1) accumulates entry e into accumulator pair (P0, P1).
// ---------------------------------------------------------------------------
#define DUAL_LOOP(EMAC, STORE0, STORE1)                                        \
    for (int vp = blockIdx.x * 8 + wid; (vp << 1) < N; vp += nwarp) {          \
        int v0 = vp << 1, v1 = v0 | 1;                                         \
        int m0 = __ldg(g_meta + v0);                                           \
        int m1 = (v1 < N) ? __ldg(g_meta + v1) : 0;                            \
        int c0 = m0 & 31, o0 = m0 >> 5;                                        \
        int c1 = m1 & 31, o1 = m1 >> 5;                                        \
        __nv_bfloat162 accA0 = bf2(0u), accA1 = bf2(0u);                       \
        __nv_bfloat162 accB0 = bf2(0u), accB1 = bf2(0u);                       \
        int jm = max(c0, c1);                                                  \
        for (int j = 0; j < jm; ++j) {                                         \
            if (j < c0) {                                                      \
                int e = __ldg(g_entries + o0 + j);                             \
                EMAC(e, accA0, accA1);                                         \
            }                                                                  \
            if (j < c1) {                                                      \
                int e = __ldg(g_entries + o1 + j);                             \
                EMAC(e, accB0, accB1);                                         \
            }                                                                  \
        }                                                                      \
        STORE0(v0, accA0, accA1);                                              \
        if (v1 < N) STORE1(v1, accB0, accB1);                                  \
    }

// ---------------------------------------------------------------------------
// conv1: x(f32,[N,8]) @ W1[27,8,32] -> g_buf32 (bf16).  lane = co.
// ---------------------------------------------------------------------------
__global__ void __launch_bounds__(256) convA_kernel(const float* __restrict__ x, int N) {
    __shared__ uint2 Wsh[KK * 64];
    for (int t = threadIdx.x; t < KK * 64; t += 256) {
        int l = t & 31, jp = (t >> 5) & 1, k = t >> 6;
        const float* wb = g_W1 + (k << 8) + l;
        int c = jp * 4;
        uint2 u;
        u.x = pk(wb[c * 32], wb[(c + 1) * 32]);
        u.y = pk(wb[(c + 2) * 32], wb[(c + 3) * 32]);
        Wsh[t] = u;
    }
    __syncthreads();
    int lane = threadIdx.x & 31, wid = threadIdx.x >> 5;
    int nwarp = gridDim.x * 8;
#define A_E(E, A0, A1)                                                    \
    {                                                                     \
        int k = (E) >> 20, s = (E) & 0xFFFFF;                             \
        const float4* p = reinterpret_cast<const float4*>(x + ((size_t)s << 3)); \
        float4 fa = __ldg(p), fb = __ldg(p + 1);                          \
        const uint2* wk = Wsh + (k << 6) + lane;                          \
        uint2 w0 = wk[0], w1 = wk[32];                                    \
        A0 = __hfma2(bf2(pk(fa.x, fa.y)), bf2(w0.x), A0);                 \
        A1 = __hfma2(bf2(pk(fa.z, fa.w)), bf2(w0.y), A1);                 \
        A0 = __hfma2(bf2(pk(fb.x, fb.y)), bf2(w1.x), A0);                 \
        A1 = __hfma2(bf2(pk(fb.z, fb.w)), bf2(w1.y), A1);                 \
    }
#define A_ST(V, P0, P1) \
    g_buf32[((size_t)(V) << 5) + lane] = __float2bfloat16(sum2(P0) + sum2(P1));
    DUAL_LOOP(A_E, A_ST, A_ST)
#undef A_E
#undef A_ST
}

// ---------------------------------------------------------------------------
// conv2: g_buf32(bf16,[N,32]) @ Wd1[27,32,8] -> g_buf8a.  co=lane&7,
// g=lane>>3 covers ci in [8g,8g+8).
// ---------------------------------------------------------------------------
__global__ void __launch_bounds__(256) convB_kernel(const float* __restrict__ W, int N) {
    __shared__ uint2 Wsh[KK * 64];
    for (int t = threadIdx.x; t < KK * 64; t += 256) {
        int l = t & 31, jp = (t >> 5) & 1, k = t >> 6;
        int g = l >> 3, co = l & 7;
        const float* wb = W + (size_t)k * 256 + co;
        int c = g * 8 + jp * 4;
        uint2 u;
        u.x = pk(wb[c * 8], wb[(c + 1) * 8]);
        u.y = pk(wb[(c + 2) * 8], wb[(c + 3) * 8]);
        Wsh[t] = u;
    }
    __syncthreads();
    int lane = threadIdx.x & 31, wid = threadIdx.x >> 5;
    int g = lane >> 3, co = lane & 7;
    int nwarp = gridDim.x * 8;
#define B_E(E, A0, A1)                                                    \
    {                                                                     \
        int k = (E) >> 20, s = (E) & 0xFFFFF;                             \
        uint4 q = __ldg(reinterpret_cast<const uint4*>(g_buf32 +          \
                                                       ((size_t)s << 5) + (g << 3))); \
        const uint2* wk = Wsh + (k << 6) + lane;                          \
        uint2 w0 = wk[0], w1 = wk[32];                                    \
        A0 = __hfma2(bf2(q.x), bf2(w0.x), A0);                            \
        A1 = __hfma2(bf2(q.y), bf2(w0.y), A1);                            \
        A0 = __hfma2(bf2(q.z), bf2(w1.x), A0);                            \
        A1 = __hfma2(bf2(q.w), bf2(w1.y), A1);                            \
    }
#define B_ST(V, P0, P1)                                                   \
    {                                                                     \
        float acc = sum2(P0) + sum2(P1);                                  \
        acc += __shfl_xor_sync(0xffffffffu, acc, 8);                      \
        acc += __shfl_xor_sync(0xffffffffu, acc, 16);                     \
        if (g == 0) g_buf8a[((size_t)(V) << 3) + co] = __float2bfloat16(acc); \
    }
    DUAL_LOOP(B_E, B_ST, B_ST)
#undef B_E
#undef B_ST
}

// ---------------------------------------------------------------------------
// conv3/conv4: 8->8.  SRC=0: buf8a->buf8b (RESID: out = x - conv),
// SRC=1: buf8b->buf8a.  co=lane&7, g=lane>>3 covers ci 2g,2g+1.
// ---------------------------------------------------------------------------
template <int SRC, int RESID>
__global__ void __launch_bounds__(256) conv88_kernel(const float* __restrict__ W,
                                                     const float* __restrict__ x, int N) {
    __shared__ u32 Wsh[KK * 32];
    for (int t = threadIdx.x; t < KK * 32; t += 256) {
        int l = t & 31, k = t >> 5;
        int g = l >> 3, co = l & 7;
        const float* wb = W + (size_t)k * 64 + co;
        Wsh[t] = pk(wb[(2 * g) * 8], wb[(2 * g + 1) * 8]);
    }
    __syncthreads();
    const __nv_bfloat16* in = (SRC == 0) ? g_buf8a : g_buf8b;
    __nv_bfloat16* out = (SRC == 0) ? g_buf8b : g_buf8a;
    int lane = threadIdx.x & 31, wid = threadIdx.x >> 5;
    int g = lane >> 3, co = lane & 7;
    int nwarp = gridDim.x * 8;
#define C_E(E, A0, A1)                                                    \
    {                                                                     \
        int k = (E) >> 20, s = (E) & 0xFFFFF;                             \
        u32 q = __ldg(reinterpret_cast<const u32*>(in + ((size_t)s << 3) + (g << 1))); \
        A0 = __hfma2(bf2(q), bf2(Wsh[(k << 5) + lane]), A0);              \
        (void)A1;                                                         \
    }
#define C_ST(V, P0, P1)                                                   \
    {                                                                     \
        float acc = sum2(P0);                                             \
        acc += __shfl_xor_sync(0xffffffffu, acc, 8);                      \
        acc += __shfl_xor_sync(0xffffffffu, acc, 16);                     \
        if (g == 0) {                                                     \
            float r = RESID ? (x[((size_t)(V) << 3) + co] - acc) : acc;   \
            out[((size_t)(V) << 3) + co] = __float2bfloat16(r);           \
        }                                                                 \
    }
    DUAL_LOOP(C_E, C_ST, C_ST)
#undef C_E
#undef C_ST
}

// ---------------------------------------------------------------------------
// conv5: g_buf8a(bf16,[N,8]) @ Wu1[27,8,32] -> g_buf32.  lane = co.
// ---------------------------------------------------------------------------
__global__ void __launch_bounds__(256) convE_kernel(const float* __restrict__ W, int N) {
    __shared__ uint2 Wsh[KK * 64];
    for (int t = threadIdx.x; t < KK * 64; t += 256) {
        int l = t & 31, jp = (t >> 5) & 1, k = t >> 6;
        const float* wb = W + (size_t)k * 256 + l;
        int c = jp * 4;
        uint2 u;
        u.x = pk(wb[c * 32], wb[(c + 1) * 32]);
        u.y = pk(wb[(c + 2) * 32], wb[(c + 3) * 32]);
        Wsh[t] = u;
    }
    __syncthreads();
    int lane = threadIdx.x & 31, wid = threadIdx.x >> 5;
    int nwarp = gridDim.x * 8;
#define E_E(E, A0, A1)                                                    \
    {                                                                     \
        int k = (E) >> 20, s = (E) & 0xFFFFF;                             \
        uint4 q = __ldg(reinterpret_cast<const uint4*>(g_buf8a + ((size_t)s << 3))); \
        const uint2* wk = Wsh + (k << 6) + lane;                          \
        uint2 w0 = wk[0], w1 = wk[32];                                    \
        A0 = __hfma2(bf2(q.x), bf2(w0.x), A0);                            \
        A1 = __hfma2(bf2(q.y), bf2(w0.y), A1);                            \
        A0 = __hfma2(bf2(q.z), bf2(w1.x), A0);                            \
        A1 = __hfma2(bf2(q.w), bf2(w1.y), A1);                            \
    }
#define E_ST(V, P0, P1) \
    g_buf32[((size_t)(V) << 5) + lane] = __float2bfloat16(sum2(P0) + sum2(P1));
    DUAL_LOOP(E_E, E_ST, E_ST)
#undef E_E
#undef E_ST
}

// ---------------------------------------------------------------------------
// conv6: g_buf32(bf16,[N,32]) @ Wu2[27,32,32] -> d_out(f32), epilogue adds
// tile(x,4).  lane = co.  Single voxel per warp iter (register pressure),
// pairwise entry unroll into independent accumulator banks.
// ---------------------------------------------------------------------------
#define WF_U2 (KK * 8 * 32)  // 6912 uint2 = 54 KB
__global__ void __launch_bounds__(256) convF_kernel(const float* __restrict__ W,
                                                    const float* __restrict__ x,
                                                    float* __restrict__ out, int N) {
    extern __shared__ uint2 Wsh[];
    for (int t = threadIdx.x; t < WF_U2; t += 256) {
        int l = t & 31, ip = (t >> 5) & 7, k = t >> 8;
        const float* wb = W + (size_t)k * 1024 + l;
        int c = ip * 4;
        uint2 u;
        u.x = pk(wb[c * 32], wb[(c + 1) * 32]);
        u.y = pk(wb[(c + 2) * 32], wb[(c + 3) * 32]);
        Wsh[t] = u;
    }
    __syncthreads();
    int lane = threadIdx.x & 31, wid = threadIdx.x >> 5;
    int nwarp = gridDim.x * 8;
#define F_E(E, A0, A1)                                                    \
    {                                                                     \
        int k = (E) >> 20, s = (E) & 0xFFFFF;                             \
        const uint4* p = reinterpret_cast<const uint4*>(g_buf32 + ((size_t)s << 5)); \
        uint4 q0 = __ldg(p), q1 = __ldg(p + 1), q2 = __ldg(p + 2), q3 = __ldg(p + 3); \
        const uint2* wk = Wsh + (k << 8) + lane;                          \
        uint2 w;                                                          \
        w = wk[0];                                                        \
        A0 = __hfma2(bf2(q0.x), bf2(w.x), A0);                            \
        A1 = __hfma2(bf2(q0.y), bf2(w.y), A1);                            \
        w = wk[32];                                                       \
        A0 = __hfma2(bf2(q0.z), bf2(w.x), A0);                            \
        A1 = __hfma2(bf2(q0.w), bf2(w.y), A1);                            \
        w = wk[64];                                                       \
        A0 = __hfma2(bf2(q1.x), bf2(w.x), A0);                            \
        A1 = __hfma2(bf2(q1.y), bf2(w.y), A1);                            \
        w = wk[96];                                                       \
        A0 = __hfma2(bf2(q1.z), bf2(w.x), A0);                            \
        A1 = __hfma2(bf2(q1.w), bf2(w.y), A1);                            \
        w = wk[128];                                                      \
        A0 = __hfma2(bf2(q2.x), bf2(w.x), A0);                            \
        A1 = __hfma2(bf2(q2.y), bf2(w.y), A1);                            \
        w = wk[160];                                                      \
        A0 = __hfma2(bf2(q2.z), bf2(w.x), A0);                            \
        A1 = __hfma2(bf2(q2.w), bf2(w.y), A1);                            \
        w = wk[192];                                                      \
        A0 = __hfma2(bf2(q3.x), bf2(w.x), A0);                            \
        A1 = __hfma2(bf2(q3.y), bf2(w.y), A1);                            \
        w = wk[224];                                                      \
        A0 = __hfma2(bf2(q3.z), bf2(w.x), A0);                            \
        A1 = __hfma2(bf2(q3.w), bf2(w.y), A1);                            \
    }
    for (int vox = blockIdx.x * 8 + wid; vox < N; vox += nwarp) {
        int m = __ldg(g_meta + vox);
        int cnt = m & 31, off = m >> 5;
        __nv_bfloat162 acc0 = bf2(0u), acc1 = bf2(0u), acc2 = bf2(0u),
                       acc3 = bf2(0u);
        int j = 0;
        for (; j + 2 <= cnt; j += 2) {
            int e0 = __ldg(g_entries + off + j);
            int e1 = __ldg(g_entries + off + j + 1);
            F_E(e0, acc0, acc1);
            F_E(e1, acc2, acc3);
        }
        if (j < cnt) {
            int e0 = __ldg(g_entries + off + j);
            F_E(e0, acc0, acc1);
        }
        float acc = (sum2(acc0) + sum2(acc1)) + (sum2(acc2) + sum2(acc3));
        out[((size_t)vox << 5) + lane] = acc + x[((size_t)vox << 3) + (lane & 7)];
    }
#undef F_E
}

// ---------------------------------------------------------------------------

extern "C" void kernel_launch(void* const* d_in, const int* in_sizes, int n_in,
                              void* d_out, int out_size) {
    const float* x = (const float*)d_in[0];
    const int* nbr = (const int*)d_in[1];
    const void* mask = d_in[2];
    const float* Wd0 = (const float*)d_in[3];
    const float* Wd1 = (const float*)d_in[4];
    const float* Wd2 = (const float*)d_in[5];
    const float* Wu0 = (const float*)d_in[6];
    const float* Wu1 = (const float*)d_in[7];
    const float* Wu2 = (const float*)d_in[8];
    float* out = (float*)d_out;

    int N = in_sizes[0] / 8;
    if (N > N_MAX) N = N_MAX;
    int nb = (N + 255) / 256;

    probe_mask_kernel<<<1, 256>>>((const unsigned char*)mask);
    count_kernel<<<nb, 256>>>(mask, N);
    scan_blocks_kernel<<<1, 1024>>>(nb);
    fill_kernel<<<nb, 256>>>(mask, nbr, N);
    fold_kernel<<<(KK * 8 * 32 + 255) / 256, 256>>>(Wd0);

    const int LB = 1184;  // 8 persistent blocks/SM on 148 SMs (measured-best)
    convA_kernel<<<LB, 256>>>(x, N);
    convB_kernel<<<LB, 256>>>(Wd1, N);
    conv88_kernel<0, 1><<<LB, 256>>>(Wd2, x, N);  // d3, then r = x - d
    conv88_kernel<1, 0><<<LB, 256>>>(Wu0, x, N);
    convE_kernel<<<LB, 256>>>(Wu1, N);

    const int smF = WF_U2 * sizeof(uint2);  // 54 KB -> 4 blocks/SM
    cudaFuncSetAttribute(convF_kernel, cudaFuncAttributeMaxDynamicSharedMemorySize, smF);
    convF_kernel<<<592, 256, smF>>>(Wu2, x, out, N);
}